// round 1
// baseline (speedup 1.0000x reference)
#include <cuda_runtime.h>
#include <cuda_bf16.h>
#include <cstddef>

#define T_STEPS 512
#define BDIM 64
#define IDIM 128
#define HDIM 1024

// double-buffered hidden state + barrier counter (static device globals: no allocs)
__device__ float g_hbuf[2][BDIM * HDIM];
__device__ unsigned int g_bar;

// ---------------------------------------------------------------------------
// init: zero barrier counter, load h0 into buffer 0
// ---------------------------------------------------------------------------
__global__ void init_kernel(const float* __restrict__ h0) {
    int i = blockIdx.x * blockDim.x + threadIdx.x;
    if (i == 0) g_bar = 0u;
    if (i < BDIM * HDIM) g_hbuf[0][i] = h0[i];
}

// ---------------------------------------------------------------------------
// Z = x @ W_ih^T + b  written into out[t*B*H + b*H + j]
// grid (16, 512): block tile 64 rows (t,b flattened) x 64 cols (j), K = 128
// ---------------------------------------------------------------------------
#define ZS 132  // padded row stride (floats) for 128-float rows
__global__ void __launch_bounds__(256, 1)
z_kernel(const float* __restrict__ x, const float* __restrict__ wih,
         const float* __restrict__ bv, float* __restrict__ out) {
    extern __shared__ float sm[];
    float* xs = sm;               // 64 x ZS
    float* ws = sm + 64 * ZS;     // 64 x ZS

    const int jbase = blockIdx.x * 64;
    const int mbase = blockIdx.y * 64;
    const int tid = threadIdx.x;

    // stage x tile and W_ih tile (row-major, float4, coalesced, conflict-free)
    for (int idx = tid; idx < 64 * 32; idx += 256) {
        int r = idx >> 5;
        int k4 = (idx & 31) << 2;
        *(float4*)&xs[r * ZS + k4] =
            *(const float4*)&x[(size_t)(mbase + r) * IDIM + k4];
        *(float4*)&ws[r * ZS + k4] =
            *(const float4*)&wih[(size_t)(jbase + r) * IDIM + k4];
    }
    __syncthreads();

    const int mq = tid >> 4;   // 0..15, rows mq + 16*i
    const int jq = tid & 15;   // 0..15, cols jq + 16*j

    float4 acc[4][4];
#pragma unroll
    for (int i = 0; i < 4; i++)
#pragma unroll
        for (int j = 0; j < 4; j++) acc[i][j] = make_float4(0.f, 0.f, 0.f, 0.f);

#pragma unroll 2
    for (int kk = 0; kk < IDIM; kk += 4) {
        float4 hv[4], wv[4];
#pragma unroll
        for (int i = 0; i < 4; i++) hv[i] = *(const float4*)&xs[(mq + 16 * i) * ZS + kk];
#pragma unroll
        for (int j = 0; j < 4; j++) wv[j] = *(const float4*)&ws[(jq + 16 * j) * ZS + kk];
#pragma unroll
        for (int i = 0; i < 4; i++)
#pragma unroll
            for (int j = 0; j < 4; j++) {
                acc[i][j].x = fmaf(hv[i].x, wv[j].x, acc[i][j].x);
                acc[i][j].y = fmaf(hv[i].y, wv[j].y, acc[i][j].y);
                acc[i][j].z = fmaf(hv[i].z, wv[j].z, acc[i][j].z);
                acc[i][j].w = fmaf(hv[i].w, wv[j].w, acc[i][j].w);
            }
    }

#pragma unroll
    for (int j = 0; j < 4; j++) {
        float bj = __ldg(&bv[jbase + jq + 16 * j]);
#pragma unroll
        for (int i = 0; i < 4; i++) {
            float s = acc[i][j].x + acc[i][j].y + acc[i][j].z + acc[i][j].w + bj;
            out[(size_t)(mbase + mq + 16 * i) * HDIM + jbase + jq + 16 * j] = s;
        }
    }
}

// ---------------------------------------------------------------------------
// persistent recurrence kernel
// grid (32, 4) = 128 blocks, 256 threads.
// block: j-tile = 32 cols (blockIdx.x), b-tile = 16 rows (blockIdx.y)
// W_hh slice (32 x 1024) lives in SMEM for all 512 steps.
// 8 warps split K=1024 into 128-slices; cross-warp reduce via smem.
// one software grid barrier per step (double-buffered h).
// ---------------------------------------------------------------------------
#define RS 1028  // padded row stride (floats) for 1024-float rows

__global__ void __launch_bounds__(256, 1)
rec_kernel(const float* __restrict__ whh, float* __restrict__ out) {
    extern __shared__ float sm[];
    float* ws = sm;                  // 32 x RS
    float* hs = sm + 32 * RS;        // 16 x RS
    float* red = hs;                 // alias: 8 x 512 floats, used after k-loop

    const int jbase = blockIdx.x * 32;
    const int bbase = blockIdx.y * 16;
    const int tid = threadIdx.x;
    const unsigned nblocks = gridDim.x * gridDim.y;  // 128

    // load resident W_hh slice (once)
    for (int idx = tid; idx < 32 * 256; idx += 256) {
        int j = idx >> 8;
        int k4 = (idx & 255) << 2;
        *(float4*)&ws[j * RS + k4] =
            *(const float4*)&whh[(size_t)(jbase + j) * HDIM + k4];
    }

    const int lane = tid & 31;
    const int w = tid >> 5;        // warp 0..7 -> K slice
    const int bq = lane >> 3;      // 0..3 : b = bq + 4*i
    const int jq = lane & 7;       // 0..7 : j = jq + 8*jj
    const int kbeg = w << 7;       // w * 128

    for (int t = 0; t < T_STEPS; t++) {
        __syncthreads();  // protect hs/red reuse (and ws load at t==0)

        // stage h tile [16 x 1024] via L2 (ldcg -> coherent across SMs)
        const float* hsrc = g_hbuf[t & 1] + (size_t)bbase * HDIM;
        for (int idx = tid; idx < 16 * 256; idx += 256) {
            int b = idx >> 8;
            int k4 = (idx & 255) << 2;
            float4 v = __ldcg((const float4*)&hsrc[b * HDIM + k4]);
            *(float4*)&hs[b * RS + k4] = v;
        }
        __syncthreads();

        float4 acc[4][4];
#pragma unroll
        for (int i = 0; i < 4; i++)
#pragma unroll
            for (int j = 0; j < 4; j++) acc[i][j] = make_float4(0.f, 0.f, 0.f, 0.f);

#pragma unroll 2
        for (int kk = 0; kk < 128; kk += 4) {
            float4 hv[4], wv[4];
#pragma unroll
            for (int i = 0; i < 4; i++)
                hv[i] = *(const float4*)&hs[(bq + 4 * i) * RS + kbeg + kk];
#pragma unroll
            for (int j = 0; j < 4; j++)
                wv[j] = *(const float4*)&ws[(jq + 8 * j) * RS + kbeg + kk];
#pragma unroll
            for (int i = 0; i < 4; i++)
#pragma unroll
                for (int j = 0; j < 4; j++) {
                    acc[i][j].x = fmaf(hv[i].x, wv[j].x, acc[i][j].x);
                    acc[i][j].y = fmaf(hv[i].y, wv[j].y, acc[i][j].y);
                    acc[i][j].z = fmaf(hv[i].z, wv[j].z, acc[i][j].z);
                    acc[i][j].w = fmaf(hv[i].w, wv[j].w, acc[i][j].w);
                }
        }
        __syncthreads();  // all warps done reading hs before red (alias) writes

        // horizontal sums -> partials  red[w][b*32 + j]
#pragma unroll
        for (int i = 0; i < 4; i++)
#pragma unroll
            for (int j = 0; j < 4; j++) {
                float s = acc[i][j].x + acc[i][j].y + acc[i][j].z + acc[i][j].w;
                int b = bq + 4 * i;
                int jj = jq + 8 * j;
                red[(w << 9) + (b << 5) + jj] = s;
            }
        __syncthreads();

        // reduce across 8 warps, add Z (already in out), tanh, write out + hbuf
#pragma unroll
        for (int r = 0; r < 2; r++) {
            int o = tid + (r << 8);   // 0..511
            float s = 0.f;
#pragma unroll
            for (int ww = 0; ww < 8; ww++) s += red[(ww << 9) + o];
            int b = o >> 5;
            int j = o & 31;
            size_t oi = (size_t)t * (BDIM * HDIM) + (size_t)(bbase + b) * HDIM + jbase + j;
            float hval = tanhf(out[oi] + s);
            out[oi] = hval;
            g_hbuf[(t + 1) & 1][(size_t)(bbase + b) * HDIM + jbase + j] = hval;
        }

        // grid barrier (release writes, arrive, spin, acquire)
        __threadfence();
        __syncthreads();
        if (tid == 0) {
            atomicAdd(&g_bar, 1u);
            unsigned target = nblocks * (unsigned)(t + 1);
            while (*(volatile unsigned int*)&g_bar < target) { }
            __threadfence();
        }
        __syncthreads();
    }
}

// ---------------------------------------------------------------------------
// h_final = outputs[T-1]
// ---------------------------------------------------------------------------
__global__ void tail_kernel(float* __restrict__ out) {
    int i = blockIdx.x * blockDim.x + threadIdx.x;
    if (i < BDIM * HDIM) {
        out[(size_t)T_STEPS * BDIM * HDIM + i] =
            out[(size_t)(T_STEPS - 1) * BDIM * HDIM + i];
    }
}

// ---------------------------------------------------------------------------
extern "C" void kernel_launch(void* const* d_in, const int* in_sizes, int n_in,
                              void* d_out, int out_size) {
    // map inputs by element count (all distinct): x, h0, w_ih, w_hh, b
    const float *x = nullptr, *h0 = nullptr, *wih = nullptr, *whh = nullptr, *bv = nullptr;
    for (int i = 0; i < n_in; i++) {
        switch (in_sizes[i]) {
            case T_STEPS * BDIM * IDIM: x   = (const float*)d_in[i]; break;  // 4194304
            case BDIM * HDIM:           h0  = (const float*)d_in[i]; break;  // 65536
            case HDIM * IDIM:           wih = (const float*)d_in[i]; break;  // 131072
            case HDIM * HDIM:           whh = (const float*)d_in[i]; break;  // 1048576
            case HDIM:                  bv  = (const float*)d_in[i]; break;  // 1024
            default: break;
        }
    }
    float* out = (float*)d_out;

    const int z_smem = 2 * 64 * ZS * sizeof(float);      // 67584
    const int r_smem = (32 + 16) * RS * sizeof(float);   // 197376
    cudaFuncSetAttribute(z_kernel,  cudaFuncAttributeMaxDynamicSharedMemorySize, z_smem);
    cudaFuncSetAttribute(rec_kernel, cudaFuncAttributeMaxDynamicSharedMemorySize, r_smem);

    init_kernel<<<256, 256>>>(h0);
    z_kernel<<<dim3(16, 512), 256, z_smem>>>(x, wih, bv, out);
    rec_kernel<<<dim3(32, 4), 256, r_smem>>>(whh, out);
    if (out_size >= T_STEPS * BDIM * HDIM + BDIM * HDIM) {
        tail_kernel<<<256, 256>>>(out);
    }
}

// round 2
// speedup vs baseline: 1.3130x; 1.3130x over previous
#include <cuda_runtime.h>
#include <cuda_bf16.h>
#include <cstddef>
#include <cstdint>

#define T_STEPS 512
#define BDIM 64
#define IDIM 128
#define HDIM 1024

typedef unsigned long long u64;

__device__ float g_hbuf[2][BDIM * HDIM];
__device__ unsigned int g_bar;

// packed fp32x2 FMA (FFMA2) — 2 MACs per instruction on the fma pipe
__device__ __forceinline__ void fma2(u64& d, u64 a, u64 b) {
    asm("fma.rn.f32x2 %0, %1, %2, %0;" : "+l"(d) : "l"(a), "l"(b));
}
__device__ __forceinline__ float2 unpack2(u64 v) {
    float2 r;
    asm("mov.b64 {%0, %1}, %2;" : "=f"(r.x), "=f"(r.y) : "l"(v));
    return r;
}

// ---------------------------------------------------------------------------
__global__ void init_kernel(const float* __restrict__ h0) {
    int i = blockIdx.x * blockDim.x + threadIdx.x;
    if (i == 0) g_bar = 0u;
    if (i < BDIM * HDIM) g_hbuf[0][i] = h0[i];
}

// ---------------------------------------------------------------------------
// Z = x @ W_ih^T + b   (tile 64x64, K=128, f32x2 packed)
// ---------------------------------------------------------------------------
#define ZS 132
__global__ void __launch_bounds__(256, 1)
z_kernel(const float* __restrict__ x, const float* __restrict__ wih,
         const float* __restrict__ bv, float* __restrict__ out) {
    extern __shared__ float sm[];
    float* xs = sm;               // 64 x ZS
    float* ws = sm + 64 * ZS;     // 64 x ZS

    const int jbase = blockIdx.x * 64;
    const int mbase = blockIdx.y * 64;
    const int tid = threadIdx.x;

    for (int idx = tid; idx < 64 * 32; idx += 256) {
        int r = idx >> 5;
        int k4 = (idx & 31) << 2;
        *(float4*)&xs[r * ZS + k4] =
            *(const float4*)&x[(size_t)(mbase + r) * IDIM + k4];
        *(float4*)&ws[r * ZS + k4] =
            *(const float4*)&wih[(size_t)(jbase + r) * IDIM + k4];
    }
    __syncthreads();

    const int mq = tid >> 4;
    const int jq = tid & 15;

    u64 acc[4][4][2];
#pragma unroll
    for (int i = 0; i < 4; i++)
#pragma unroll
        for (int j = 0; j < 4; j++) { acc[i][j][0] = 0ull; acc[i][j][1] = 0ull; }

#pragma unroll 2
    for (int kk = 0; kk < IDIM; kk += 4) {
        ulonglong2 hv[4], wv[4];
#pragma unroll
        for (int i = 0; i < 4; i++)
            hv[i] = *(const ulonglong2*)&xs[(mq + 16 * i) * ZS + kk];
#pragma unroll
        for (int j = 0; j < 4; j++)
            wv[j] = *(const ulonglong2*)&ws[(jq + 16 * j) * ZS + kk];
#pragma unroll
        for (int i = 0; i < 4; i++)
#pragma unroll
            for (int j = 0; j < 4; j++) {
                fma2(acc[i][j][0], hv[i].x, wv[j].x);
                fma2(acc[i][j][1], hv[i].y, wv[j].y);
            }
    }

#pragma unroll
    for (int j = 0; j < 4; j++) {
        float bj = __ldg(&bv[jbase + jq + 16 * j]);
#pragma unroll
        for (int i = 0; i < 4; i++) {
            float2 a = unpack2(acc[i][j][0]);
            float2 c = unpack2(acc[i][j][1]);
            float s = (a.x + a.y) + (c.x + c.y) + bj;
            out[(size_t)(mbase + mq + 16 * i) * HDIM + jbase + jq + 16 * j] = s;
        }
    }
}

// ---------------------------------------------------------------------------
// persistent recurrence: 128 blocks (32 j-tiles x 4 b-tiles), 256 threads.
// W_hh slice SMEM-resident for 512 steps; f32x2 packed FMA; cp.async staging;
// single-thread fence+atomic grid barrier.
// ---------------------------------------------------------------------------
#define RS 1028

__global__ void __launch_bounds__(256, 1)
rec_kernel(const float* __restrict__ whh, float* __restrict__ out) {
    extern __shared__ float sm[];
    float* ws = sm;                  // 32 x RS
    float* hs = sm + 32 * RS;        // 16 x RS
    float* red = hs;                 // alias, used after k-loop

    const int jbase = blockIdx.x * 32;
    const int bbase = blockIdx.y * 16;
    const int tid = threadIdx.x;
    const unsigned nblocks = gridDim.x * gridDim.y;  // 128

    // resident W_hh slice
    for (int idx = tid; idx < 32 * 256; idx += 256) {
        int j = idx >> 8;
        int k4 = (idx & 255) << 2;
        *(float4*)&ws[j * RS + k4] =
            *(const float4*)&whh[(size_t)(jbase + j) * HDIM + k4];
    }

    const int lane = tid & 31;
    const int w = tid >> 5;
    const int bq = lane >> 3;
    const int jq = lane & 7;
    const int kbeg = w << 7;

    const uint32_t hs_s = (uint32_t)__cvta_generic_to_shared(hs);

    // epilogue output coordinates (fixed per thread, shifted by t)
    const int o0 = tid, o1 = tid + 256;
    const size_t oi0_base = (size_t)(bbase + (o0 >> 5)) * HDIM + jbase + (o0 & 31);
    const size_t oi1_base = (size_t)(bbase + (o1 >> 5)) * HDIM + jbase + (o1 & 31);
    const size_t hb0 = oi0_base, hb1 = oi1_base;  // same layout in g_hbuf

    // cp.async source/dst (fixed per thread)
    const int sb = tid >> 4;              // 0..15 row
    const int sk = (tid & 15) << 6;       // 0..960, 16 float4 chunks of 4 floats... (see loop)

    for (int t = 0; t < T_STEPS; t++) {
        // ---- stage h tile [16 x 1024] via cp.async (L2 path, coherent) ----
        const float* hsrc = g_hbuf[t & 1] + (size_t)bbase * HDIM;
#pragma unroll
        for (int it = 0; it < 16; it++) {
            int idx = tid + (it << 8);        // 0..4095
            int b = idx >> 8;
            int k4 = (idx & 255) << 2;
            uint32_t dst = hs_s + (uint32_t)(b * RS + k4) * 4u;
            const float* src = hsrc + b * HDIM + k4;
            asm volatile("cp.async.cg.shared.global [%0], [%1], 16;"
                         :: "r"(dst), "l"(src));
        }
        asm volatile("cp.async.commit_group;" ::: "memory");

        // prefetch Z while copies are in flight (block-private locations)
        const size_t tb = (size_t)t * (BDIM * HDIM);
        float z0 = out[tb + oi0_base];
        float z1 = out[tb + oi1_base];

        asm volatile("cp.async.wait_group 0;" ::: "memory");
        __syncthreads();

        // ---- k-loop: 16 b x 32 j outer product over this warp's 128-k slice
        u64 acc[4][4][2];
#pragma unroll
        for (int i = 0; i < 4; i++)
#pragma unroll
            for (int j = 0; j < 4; j++) { acc[i][j][0] = 0ull; acc[i][j][1] = 0ull; }

#pragma unroll 2
        for (int kk = 0; kk < 128; kk += 4) {
            ulonglong2 hv[4], wv[4];
#pragma unroll
            for (int i = 0; i < 4; i++)
                hv[i] = *(const ulonglong2*)&hs[(bq + 4 * i) * RS + kbeg + kk];
#pragma unroll
            for (int j = 0; j < 4; j++)
                wv[j] = *(const ulonglong2*)&ws[(jq + 8 * j) * RS + kbeg + kk];
#pragma unroll
            for (int i = 0; i < 4; i++)
#pragma unroll
                for (int j = 0; j < 4; j++) {
                    fma2(acc[i][j][0], hv[i].x, wv[j].x);
                    fma2(acc[i][j][1], hv[i].y, wv[j].y);
                }
        }
        __syncthreads();  // all warps done reading hs before red (alias) writes

        // ---- horizontal sums -> red[w][b*32 + j] ----
#pragma unroll
        for (int i = 0; i < 4; i++)
#pragma unroll
            for (int j = 0; j < 4; j++) {
                float2 a = unpack2(acc[i][j][0]);
                float2 c = unpack2(acc[i][j][1]);
                float s = (a.x + a.y) + (c.x + c.y);
                red[(w << 9) + ((bq + 4 * i) << 5) + (jq + 8 * j)] = s;
            }
        __syncthreads();

        // ---- reduce 8 warps, + Z, tanh, write out + next hbuf ----
        float s0 = 0.f, s1 = 0.f;
#pragma unroll
        for (int ww = 0; ww < 8; ww++) {
            s0 += red[(ww << 9) + o0];
            s1 += red[(ww << 9) + o1];
        }
        float h0v = tanhf(z0 + s0);
        float h1v = tanhf(z1 + s1);
        out[tb + oi0_base] = h0v;
        out[tb + oi1_base] = h1v;
        float* hnext = g_hbuf[(t + 1) & 1];
        hnext[hb0] = h0v;
        hnext[hb1] = h1v;

        // ---- grid barrier: block-level sync, single-thread fence+atomic ----
        __syncthreads();
        if (tid == 0) {
            __threadfence();
            atomicAdd(&g_bar, 1u);
            const unsigned target = nblocks * (unsigned)(t + 1);
            while (*(volatile unsigned int*)&g_bar < target) { }
        }
        __syncthreads();
    }
}

// ---------------------------------------------------------------------------
__global__ void tail_kernel(float* __restrict__ out) {
    int i = blockIdx.x * blockDim.x + threadIdx.x;
    if (i < BDIM * HDIM) {
        out[(size_t)T_STEPS * BDIM * HDIM + i] =
            out[(size_t)(T_STEPS - 1) * BDIM * HDIM + i];
    }
}

// ---------------------------------------------------------------------------
extern "C" void kernel_launch(void* const* d_in, const int* in_sizes, int n_in,
                              void* d_out, int out_size) {
    const float *x = nullptr, *h0 = nullptr, *wih = nullptr, *whh = nullptr, *bv = nullptr;
    for (int i = 0; i < n_in; i++) {
        switch (in_sizes[i]) {
            case T_STEPS * BDIM * IDIM: x   = (const float*)d_in[i]; break;
            case BDIM * HDIM:           h0  = (const float*)d_in[i]; break;
            case HDIM * IDIM:           wih = (const float*)d_in[i]; break;
            case HDIM * HDIM:           whh = (const float*)d_in[i]; break;
            case HDIM:                  bv  = (const float*)d_in[i]; break;
            default: break;
        }
    }
    float* out = (float*)d_out;

    const int z_smem = 2 * 64 * ZS * sizeof(float);
    const int r_smem = (32 + 16) * RS * sizeof(float);
    cudaFuncSetAttribute(z_kernel,   cudaFuncAttributeMaxDynamicSharedMemorySize, z_smem);
    cudaFuncSetAttribute(rec_kernel, cudaFuncAttributeMaxDynamicSharedMemorySize, r_smem);

    init_kernel<<<256, 256>>>(h0);
    z_kernel<<<dim3(16, 512), 256, z_smem>>>(x, wih, bv, out);
    rec_kernel<<<dim3(32, 4), 256, r_smem>>>(whh, out);
    if (out_size >= T_STEPS * BDIM * HDIM + BDIM * HDIM) {
        tail_kernel<<<256, 256>>>(out);
    }
}

// round 3
// speedup vs baseline: 1.4076x; 1.0721x over previous
#include <cuda_runtime.h>
#include <cuda_bf16.h>
#include <cstddef>
#include <cstdint>

#define T_STEPS 512
#define BDIM 64
#define IDIM 128
#define HDIM 1024

typedef unsigned long long u64;

__device__ float g_hbuf[2][BDIM * HDIM];
__device__ unsigned int g_bar4[4 * 32];   // one counter per b-group, 128B apart

// packed fp32x2 FMA (FFMA2) — 2 MACs per instruction on the fma pipe
__device__ __forceinline__ void fma2(u64& d, u64 a, u64 b) {
    asm("fma.rn.f32x2 %0, %1, %2, %0;" : "+l"(d) : "l"(a), "l"(b));
}
__device__ __forceinline__ float2 unpack2(u64 v) {
    float2 r;
    asm("mov.b64 {%0, %1}, %2;" : "=f"(r.x), "=f"(r.y) : "l"(v));
    return r;
}

// tanh via exp: ~1e-6 rel err (MUFU ex2 + approx div), safe for 1e-3 threshold
__device__ __forceinline__ float fast_tanh(float x) {
    float e = __expf(2.0f * x);
    return 1.0f - __fdividef(2.0f, e + 1.0f);
}

// ---------------------------------------------------------------------------
__global__ void init_kernel(const float* __restrict__ h0) {
    int i = blockIdx.x * blockDim.x + threadIdx.x;
    if (i < 4 * 32) g_bar4[i] = 0u;
    if (i < BDIM * HDIM) g_hbuf[0][i] = h0[i];
}

// ---------------------------------------------------------------------------
// Z = x @ W_ih^T + b   (tile 64x64, K=128, f32x2 packed)
// ---------------------------------------------------------------------------
#define ZS 132
__global__ void __launch_bounds__(256, 1)
z_kernel(const float* __restrict__ x, const float* __restrict__ wih,
         const float* __restrict__ bv, float* __restrict__ out) {
    extern __shared__ float sm[];
    float* xs = sm;               // 64 x ZS
    float* ws = sm + 64 * ZS;     // 64 x ZS

    const int jbase = blockIdx.x * 64;
    const int mbase = blockIdx.y * 64;
    const int tid = threadIdx.x;

    for (int idx = tid; idx < 64 * 32; idx += 256) {
        int r = idx >> 5;
        int k4 = (idx & 31) << 2;
        *(float4*)&xs[r * ZS + k4] =
            *(const float4*)&x[(size_t)(mbase + r) * IDIM + k4];
        *(float4*)&ws[r * ZS + k4] =
            *(const float4*)&wih[(size_t)(jbase + r) * IDIM + k4];
    }
    __syncthreads();

    const int mq = tid >> 4;
    const int jq = tid & 15;

    u64 acc[4][4][2];
#pragma unroll
    for (int i = 0; i < 4; i++)
#pragma unroll
        for (int j = 0; j < 4; j++) { acc[i][j][0] = 0ull; acc[i][j][1] = 0ull; }

#pragma unroll 2
    for (int kk = 0; kk < IDIM; kk += 4) {
        ulonglong2 hv[4], wv[4];
#pragma unroll
        for (int i = 0; i < 4; i++)
            hv[i] = *(const ulonglong2*)&xs[(mq + 16 * i) * ZS + kk];
#pragma unroll
        for (int j = 0; j < 4; j++)
            wv[j] = *(const ulonglong2*)&ws[(jq + 16 * j) * ZS + kk];
#pragma unroll
        for (int i = 0; i < 4; i++)
#pragma unroll
            for (int j = 0; j < 4; j++) {
                fma2(acc[i][j][0], hv[i].x, wv[j].x);
                fma2(acc[i][j][1], hv[i].y, wv[j].y);
            }
    }

#pragma unroll
    for (int j = 0; j < 4; j++) {
        float bj = __ldg(&bv[jbase + jq + 16 * j]);
#pragma unroll
        for (int i = 0; i < 4; i++) {
            float2 a = unpack2(acc[i][j][0]);
            float2 c = unpack2(acc[i][j][1]);
            float s = (a.x + a.y) + (c.x + c.y) + bj;
            out[(size_t)(mbase + mq + 16 * i) * HDIM + jbase + jq + 16 * j] = s;
        }
    }
}

// ---------------------------------------------------------------------------
// persistent recurrence: 128 blocks = 32 j-tiles x 4 independent b-groups.
// W_hh slice SMEM-resident; warp-private h staging (no block sync needed);
// dedicated red buffer; per-group 32-block barrier; f32x2 FMA; fast tanh.
// ---------------------------------------------------------------------------
#define RS 1028

__global__ void __launch_bounds__(256, 1)
rec_kernel(const float* __restrict__ whh, float* __restrict__ out) {
    extern __shared__ float sm[];
    float* ws = sm;                    // 32 x RS  (W_hh slice, resident)
    float* hs = sm + 32 * RS;          // 16 x RS  (h tile)
    float* red = sm + 48 * RS;         // 8 x 512  (cross-warp partials)

    const int jbase = blockIdx.x * 32;
    const int group = blockIdx.y;          // 0..3
    const int bbase = group * 16;

    const int tid = threadIdx.x;

    // resident W_hh slice
    for (int idx = tid; idx < 32 * 256; idx += 256) {
        int j = idx >> 8;
        int k4 = (idx & 255) << 2;
        *(float4*)&ws[j * RS + k4] =
            *(const float4*)&whh[(size_t)(jbase + j) * HDIM + k4];
    }

    const int lane = tid & 31;
    const int w = tid >> 5;        // warp id -> k slice
    const int bq = lane >> 3;
    const int jq = lane & 7;
    const int kbeg = w << 7;       // w * 128

    // warp-private staging addresses: warp w copies columns [kbeg, kbeg+128)
    // of all 16 rows; each lane moves one 16B chunk per row.
    const uint32_t hs_s = (uint32_t)__cvta_generic_to_shared(hs);
    const uint32_t st_dst0 = hs_s + (uint32_t)(kbeg + lane * 4) * 4u;
    const int st_src0 = kbeg + lane * 4;

    // epilogue coordinates
    const int o0 = tid, o1 = tid + 256;
    const size_t oi0_base = (size_t)(bbase + (o0 >> 5)) * HDIM + jbase + (o0 & 31);
    const size_t oi1_base = (size_t)(bbase + (o1 >> 5)) * HDIM + jbase + (o1 & 31);

    volatile unsigned int* bar = &g_bar4[group * 32];

    __syncthreads();  // ws visible to all warps before first k-loop

    for (int t = 0; t < T_STEPS; t++) {
        // ---- warp-private h staging via cp.async (L2-coherent path) ----
        const float* hsrc = g_hbuf[t & 1] + (size_t)bbase * HDIM;
#pragma unroll
        for (int r = 0; r < 16; r++) {
            uint32_t dst = st_dst0 + (uint32_t)(r * RS) * 4u;
            const float* src = hsrc + r * HDIM + st_src0;
            asm volatile("cp.async.cg.shared.global [%0], [%1], 16;"
                         :: "r"(dst), "l"(src));
        }
        asm volatile("cp.async.commit_group;" ::: "memory");

        // prefetch Z while copies are in flight (block-private locations)
        const size_t tb = (size_t)t * (BDIM * HDIM);
        float z0 = out[tb + oi0_base];
        float z1 = out[tb + oi1_base];

        asm volatile("cp.async.wait_group 0;" ::: "memory");
        __syncwarp();

        // ---- k-loop over this warp's 128-k slice ----
        u64 acc[4][4][2];
#pragma unroll
        for (int i = 0; i < 4; i++)
#pragma unroll
            for (int j = 0; j < 4; j++) { acc[i][j][0] = 0ull; acc[i][j][1] = 0ull; }

#pragma unroll 2
        for (int kk = 0; kk < 128; kk += 4) {
            ulonglong2 hv[4], wv[4];
#pragma unroll
            for (int i = 0; i < 4; i++)
                hv[i] = *(const ulonglong2*)&hs[(bq + 4 * i) * RS + kbeg + kk];
#pragma unroll
            for (int j = 0; j < 4; j++)
                wv[j] = *(const ulonglong2*)&ws[(jq + 8 * j) * RS + kbeg + kk];
#pragma unroll
            for (int i = 0; i < 4; i++)
#pragma unroll
                for (int j = 0; j < 4; j++) {
                    fma2(acc[i][j][0], hv[i].x, wv[j].x);
                    fma2(acc[i][j][1], hv[i].y, wv[j].y);
                }
        }

        // ---- horizontal sums -> red[w][b*32 + j] (warp-private region) ----
#pragma unroll
        for (int i = 0; i < 4; i++)
#pragma unroll
            for (int j = 0; j < 4; j++) {
                float2 a = unpack2(acc[i][j][0]);
                float2 c = unpack2(acc[i][j][1]);
                float s = (a.x + a.y) + (c.x + c.y);
                red[(w << 9) + ((bq + 4 * i) << 5) + (jq + 8 * j)] = s;
            }
        __syncthreads();

        // ---- reduce 8 warps, + Z, tanh, write out + next hbuf ----
        float s0 = 0.f, s1 = 0.f;
#pragma unroll
        for (int ww = 0; ww < 8; ww++) {
            s0 += red[(ww << 9) + o0];
            s1 += red[(ww << 9) + o1];
        }
        float h0v = fast_tanh(z0 + s0);
        float h1v = fast_tanh(z1 + s1);
        out[tb + oi0_base] = h0v;
        out[tb + oi1_base] = h1v;
        float* hnext = g_hbuf[(t + 1) & 1];
        hnext[oi0_base] = h0v;
        hnext[oi1_base] = h1v;

        // ---- per-group grid barrier (32 blocks) ----
        __syncthreads();
        if (tid == 0) {
            __threadfence();
            atomicAdd((unsigned int*)bar, 1u);
            const unsigned target = 32u * (unsigned)(t + 1);
            while (*bar < target) { }
            __threadfence();
        }
        __syncthreads();
    }
}

// ---------------------------------------------------------------------------
__global__ void tail_kernel(float* __restrict__ out) {
    int i = blockIdx.x * blockDim.x + threadIdx.x;
    if (i < BDIM * HDIM) {
        out[(size_t)T_STEPS * BDIM * HDIM + i] =
            out[(size_t)(T_STEPS - 1) * BDIM * HDIM + i];
    }
}

// ---------------------------------------------------------------------------
extern "C" void kernel_launch(void* const* d_in, const int* in_sizes, int n_in,
                              void* d_out, int out_size) {
    const float *x = nullptr, *h0 = nullptr, *wih = nullptr, *whh = nullptr, *bv = nullptr;
    for (int i = 0; i < n_in; i++) {
        switch (in_sizes[i]) {
            case T_STEPS * BDIM * IDIM: x   = (const float*)d_in[i]; break;
            case BDIM * HDIM:           h0  = (const float*)d_in[i]; break;
            case HDIM * IDIM:           wih = (const float*)d_in[i]; break;
            case HDIM * HDIM:           whh = (const float*)d_in[i]; break;
            case HDIM:                  bv  = (const float*)d_in[i]; break;
            default: break;
        }
    }
    float* out = (float*)d_out;

    const int z_smem = 2 * 64 * ZS * sizeof(float);
    const int r_smem = 48 * RS * sizeof(float) + 8 * 512 * sizeof(float);  // 213760
    cudaFuncSetAttribute(z_kernel,   cudaFuncAttributeMaxDynamicSharedMemorySize, z_smem);
    cudaFuncSetAttribute(rec_kernel, cudaFuncAttributeMaxDynamicSharedMemorySize, r_smem);

    init_kernel<<<256, 256>>>(h0);
    z_kernel<<<dim3(16, 512), 256, z_smem>>>(x, wih, bv, out);
    rec_kernel<<<dim3(32, 4), 256, r_smem>>>(whh, out);
    if (out_size >= T_STEPS * BDIM * HDIM + BDIM * HDIM) {
        tail_kernel<<<256, 256>>>(out);
    }
}